// round 2
// baseline (speedup 1.0000x reference)
#include <cuda_runtime.h>
#include <cstdint>

typedef unsigned long long u64;

// ---- packed f32x2 helpers (Blackwell FFMA2 path; only reachable via PTX) ----
__device__ __forceinline__ u64 pk2(float lo, float hi) {
    u64 r; asm("mov.b64 %0, {%1, %2};" : "=l"(r) : "f"(lo), "f"(hi)); return r;
}
__device__ __forceinline__ void upk2(u64 v, float& lo, float& hi) {
    asm("mov.b64 {%0, %1}, %2;" : "=f"(lo), "=f"(hi) : "l"(v));
}
__device__ __forceinline__ u64 mul2(u64 a, u64 b) {
    u64 r; asm("mul.rn.f32x2 %0, %1, %2;" : "=l"(r) : "l"(a), "l"(b)); return r;
}
__device__ __forceinline__ u64 add2(u64 a, u64 b) {
    u64 r; asm("add.rn.f32x2 %0, %1, %2;" : "=l"(r) : "l"(a), "l"(b)); return r;
}
__device__ __forceinline__ u64 fma2(u64 a, u64 b, u64 c) {
    u64 r; asm("fma.rn.f32x2 %0, %1, %2, %3;" : "=l"(r) : "l"(a), "l"(b), "l"(c)); return r;
}

// SIR RK4: 199 steps of dt=100/199, 8 substeps each. Each thread integrates
// TWO batch elements packed in f32x2 lanes. Output (B, 200, 3) f32; results
// are buffered 4 timesteps (12 floats = 3 x float4, 48B-aligned) per element
// before store to keep L1 wavefront count down.
__global__ void __launch_bounds__(32) sir_rk4(const float* __restrict__ params,
                                              float* __restrict__ out, int n)
{
    const int gid = blockIdx.x * 32 + threadIdx.x;
    const int b0 = gid * 2;
    if (b0 + 1 >= n) return;

    const float4 pA = reinterpret_cast<const float4*>(params)[b0];
    const float4 pB = reinterpret_cast<const float4*>(params)[b0 + 1];

    const float hf  = (100.0f / 199.0f) / 8.0f;
    const float h2f = 0.5f * hf;
    const float h6f = hf / 6.0f;

    const u64 BETA = pk2(pA.x, pB.x);
    const u64 GAM  = pk2(pA.y, pB.y);
    const u64 GNEG = pk2(-pA.y, -pB.y);
    const u64 H2   = pk2(h2f,  h2f);
    const u64 NH2  = pk2(-h2f, -h2f);
    const u64 HH   = pk2(hf,   hf);
    const u64 NHH  = pk2(-hf,  -hf);
    const u64 H6   = pk2(h6f,  h6f);
    const u64 NH6  = pk2(-h6f, -h6f);
    const u64 TWO  = pk2(2.0f, 2.0f);

    u64 S = pk2(pA.z, pB.z);
    u64 I = pk2(pA.w, pB.w);
    u64 R = pk2((1.0f - pA.z) - pA.w, (1.0f - pB.z) - pB.w);

    float4* oA = reinterpret_cast<float4*>(out + (size_t)b0 * 600);
    float4* oB = reinterpret_cast<float4*>(out + (size_t)(b0 + 1) * 600);

    u64 bS[4], bI[4], bR[4];

    // One RK4 substep (31 packed FMA-pipe ops). dS=-bSI, dI=bSI-gI, dR=gI,
    // with sum_R = gamma*(I1 + 2*I2 + 2*I3 + I4) by distributivity.
    auto substep = [&]() {
        // stage 1
        u64 p1   = mul2(S, I);
        u64 bSI1 = mul2(BETA, p1);
        u64 dI1  = fma2(GNEG, I, bSI1);
        // stage 2
        u64 S2   = fma2(NH2, bSI1, S);
        u64 I2   = fma2(H2, dI1, I);
        u64 p2   = mul2(S2, I2);
        u64 bSI2 = mul2(BETA, p2);
        u64 dI2  = fma2(GNEG, I2, bSI2);
        // stage 3
        u64 S3   = fma2(NH2, bSI2, S);
        u64 I3   = fma2(H2, dI2, I);
        u64 p3   = mul2(S3, I3);
        u64 bSI3 = mul2(BETA, p3);
        u64 dI3  = fma2(GNEG, I3, bSI3);
        // stage 4
        u64 S4   = fma2(NHH, bSI3, S);
        u64 I4   = fma2(HH, dI3, I);
        u64 p4   = mul2(S4, I4);
        u64 bSI4 = mul2(BETA, p4);
        u64 dI4  = fma2(GNEG, I4, bSI4);
        // combine
        u64 tS = add2(bSI2, bSI3);
        u64 uS = add2(bSI1, bSI4);
        u64 sS = fma2(TWO, tS, uS);
        u64 tI = add2(dI2, dI3);
        u64 uI = add2(dI1, dI4);
        u64 sI = fma2(TWO, tI, uI);
        u64 tR = add2(I2, I3);
        u64 uR = add2(I, I4);
        u64 lR = fma2(TWO, tR, uR);
        u64 sR = mul2(GAM, lR);
        S = fma2(NH6, sS, S);
        I = fma2(H6, sI, I);
        R = fma2(H6, sR, R);
    };

    auto step = [&]() {
        #pragma unroll
        for (int s = 0; s < 8; s++) substep();
    };

    auto flush = [&](int c) {
        float sa[4], ia[4], ra[4], sb[4], ib[4], rb[4];
        #pragma unroll
        for (int j = 0; j < 4; j++) {
            upk2(bS[j], sa[j], sb[j]);
            upk2(bI[j], ia[j], ib[j]);
            upk2(bR[j], ra[j], rb[j]);
        }
        float4* a = oA + c * 3;
        float4* b = oB + c * 3;
        a[0] = make_float4(sa[0], ia[0], ra[0], sa[1]);
        a[1] = make_float4(ia[1], ra[1], sa[2], ia[2]);
        a[2] = make_float4(ra[2], sa[3], ia[3], ra[3]);
        b[0] = make_float4(sb[0], ib[0], rb[0], sb[1]);
        b[1] = make_float4(ib[1], rb[1], sb[2], ib[2]);
        b[2] = make_float4(rb[2], sb[3], ib[3], rb[3]);
    };

    // chunk 0: y0 plus 3 integrated steps
    bS[0] = S; bI[0] = I; bR[0] = R;
    #pragma unroll
    for (int j = 1; j < 4; j++) { step(); bS[j] = S; bI[j] = I; bR[j] = R; }
    flush(0);

    // chunks 1..49: 4 integrated steps each (total 3 + 49*4 = 199 steps)
    #pragma unroll 1
    for (int c = 1; c < 50; c++) {
        #pragma unroll
        for (int j = 0; j < 4; j++) { step(); bS[j] = S; bI[j] = I; bR[j] = R; }
        flush(c);
    }
}

extern "C" void kernel_launch(void* const* d_in, const int* in_sizes, int n_in,
                              void* d_out, int out_size)
{
    const float* params = (const float*)d_in[0];
    float* out = (float*)d_out;
    const int n = in_sizes[0] / 4;        // batch elements (65536)
    const int nthreads = (n + 1) / 2;     // 2 elements per thread (f32x2)
    const int blocks = (nthreads + 31) / 32;
    sir_rk4<<<blocks, 32>>>(params, out, n);
}